// round 4
// baseline (speedup 1.0000x reference)
#include <cuda_runtime.h>
#include <cuda_bf16.h>
#include <cstdint>

#define B_  2
#define S_  2048
#define D_  4096
#define H_  32
#define HD_ 128
#define MTOK (B_*S_)
#define NELEM ((size_t)MTOK * D_)

// ---------------- scratch (allocation-free) ----------------
__device__ __nv_bfloat16 g_xh[NELEM],  g_xl[NELEM];
__device__ __nv_bfloat16 g_wqh[NELEM], g_wql[NELEM];
__device__ __nv_bfloat16 g_wkh[NELEM], g_wkl[NELEM];
__device__ __nv_bfloat16 g_wvh[NELEM], g_wvl[NELEM];
__device__ __nv_bfloat16 g_woh[NELEM], g_wol[NELEM];
__device__ __nv_bfloat16 g_qh[NELEM],  g_ql[NELEM];
__device__ __nv_bfloat16 g_kh[NELEM],  g_kl[NELEM];
__device__ __nv_bfloat16 g_vh[NELEM],  g_vl[NELEM];
__device__ __nv_bfloat16 g_ah[NELEM],  g_al[NELEM];

// ---------------- helpers ----------------
__device__ __forceinline__ uint32_t smem_u32(const void* p) {
    return (uint32_t)__cvta_generic_to_shared(p);
}
__device__ __forceinline__ void cp16(void* dst, const void* src) {
    asm volatile("cp.async.cg.shared.global [%0], [%1], 16;"
                 :: "r"(smem_u32(dst)), "l"(src) : "memory");
}
__device__ __forceinline__ void cp_commit() {
    asm volatile("cp.async.commit_group;" ::: "memory");
}
template<int N>
__device__ __forceinline__ void cp_wait() {
    asm volatile("cp.async.wait_group %0;" :: "n"(N) : "memory");
}
__device__ __forceinline__ void ldm_x4(uint32_t& r0, uint32_t& r1, uint32_t& r2, uint32_t& r3, uint32_t addr) {
    asm volatile("ldmatrix.sync.aligned.m8n8.x4.shared.b16 {%0,%1,%2,%3}, [%4];"
                 : "=r"(r0), "=r"(r1), "=r"(r2), "=r"(r3) : "r"(addr));
}
__device__ __forceinline__ void ldm_x4_t(uint32_t& r0, uint32_t& r1, uint32_t& r2, uint32_t& r3, uint32_t addr) {
    asm volatile("ldmatrix.sync.aligned.m8n8.x4.trans.shared.b16 {%0,%1,%2,%3}, [%4];"
                 : "=r"(r0), "=r"(r1), "=r"(r2), "=r"(r3) : "r"(addr));
}
__device__ __forceinline__ void mma_bf16(float* c, const uint32_t* a, const uint32_t* b) {
    asm volatile(
        "mma.sync.aligned.m16n8k16.row.col.f32.bf16.bf16.f32 "
        "{%0,%1,%2,%3}, {%4,%5,%6,%7}, {%8,%9}, {%0,%1,%2,%3};"
        : "+f"(c[0]), "+f"(c[1]), "+f"(c[2]), "+f"(c[3])
        : "r"(a[0]), "r"(a[1]), "r"(a[2]), "r"(a[3]), "r"(b[0]), "r"(b[1]));
}
__device__ __forceinline__ void split_pack(float a, float b, uint32_t& hi, uint32_t& lo) {
    __nv_bfloat16 ha = __float2bfloat16_rn(a);
    __nv_bfloat16 hb = __float2bfloat16_rn(b);
    __nv_bfloat16 la = __float2bfloat16_rn(a - __bfloat162float(ha));
    __nv_bfloat16 lb = __float2bfloat16_rn(b - __bfloat162float(hb));
    union { __nv_bfloat162 v; uint32_t u; } ch, cl;
    ch.v = __halves2bfloat162(ha, hb);
    cl.v = __halves2bfloat162(la, lb);
    hi = ch.u; lo = cl.u;
}

// ---------------- convert: fp32 -> bf16 hi/lo ----------------
__global__ void cvt_split(const float4* __restrict__ in,
                          uint2* __restrict__ hi, uint2* __restrict__ lo, int n4) {
    int i = blockIdx.x * blockDim.x + threadIdx.x;
    if (i >= n4) return;
    float4 v = in[i];
    uint32_t h01, l01, h23, l23;
    split_pack(v.x, v.y, h01, l01);
    split_pack(v.z, v.w, h23, l23);
    hi[i] = make_uint2(h01, h23);
    lo[i] = make_uint2(l01, l23);
}

// ============ GEMM: C[M,N] = A[M,K]*B[N,K]^T, 128x256x32, bf16x3, 3-stage ============
#define GBM 128
#define GBN 256
#define GBK 32
#define GLD 40
#define GSTG 3
#define SA_ELEMS (GBM * GLD)                     // 5120
#define SB_ELEMS (GBN * GLD)                     // 10240
#define STAGE_ELEMS (2 * SA_ELEMS + 2 * SB_ELEMS) // 30720 bf16 = 60KB
#define GEMM_SMEM (GSTG * STAGE_ELEMS * 2)        // 184320 B

// OUT: 0 = fp32 C ; 1 = bf16 hi/lo C ; 2 = RoPE + bf16 hi/lo C
template<int OUT>
__global__ __launch_bounds__(256, 1)
void gemm_nt(const __nv_bfloat16* __restrict__ Ahg, const __nv_bfloat16* __restrict__ Alg,
             const __nv_bfloat16* __restrict__ Bhg, const __nv_bfloat16* __restrict__ Blg,
             float* __restrict__ C,
             __nv_bfloat16* __restrict__ Chg, __nv_bfloat16* __restrict__ Clg,
             const float* __restrict__ fc, const float* __restrict__ fs) {
    extern __shared__ __align__(16) __nv_bfloat16 sm[];

    const int tid = threadIdx.x;
    const int wid = tid >> 5, lane = tid & 31;
    const int wm = wid >> 2, wn = wid & 3;              // 2 x 4 warp grid, warp tile 64x64
    const int m0 = blockIdx.x * GBM, n0 = blockIdx.y * GBN;
    const int lrow = lane & 15, lcol8 = (lane >> 4) << 3;
    const int g = lane >> 2, tq = lane & 3;
    const int K = D_;

    float acc[4][8][4];
#pragma unroll
    for (int i = 0; i < 4; i++)
#pragma unroll
        for (int j = 0; j < 8; j++)
#pragma unroll
            for (int e = 0; e < 4; e++) acc[i][j][e] = 0.f;

    auto load_stage = [&](int kb, int buf) {
        __nv_bfloat16* base = sm + buf * STAGE_ELEMS;
        const int k0 = kb * GBK;
#pragma unroll
        for (int p = 0; p < 12; p++) {
            const int t = tid + p * 256;
            if (t < 1024) {            // A hi / lo: 512 chunks each
                const int pair = t >> 9;
                const int i = t & 511;
                const int row = i >> 2, col8 = (i & 3) << 3;
                const __nv_bfloat16* gsrc = (pair ? Alg : Ahg) + (size_t)(m0 + row) * K + k0 + col8;
                cp16(base + pair * SA_ELEMS + row * GLD + col8, gsrc);
            } else {                   // B hi / lo: 1024 chunks each
                const int t2 = t - 1024;
                const int pair = t2 >> 10;
                const int i = t2 & 1023;
                const int row = i >> 2, col8 = (i & 3) << 3;
                const __nv_bfloat16* gsrc = (pair ? Blg : Bhg) + (size_t)(n0 + row) * K + k0 + col8;
                cp16(base + 2 * SA_ELEMS + pair * SB_ELEMS + row * GLD + col8, gsrc);
            }
        }
    };

    const int KT = K / GBK;            // 128
    load_stage(0, 0); cp_commit();
    load_stage(1, 1); cp_commit();

    for (int kb = 0; kb < KT; kb++) {
        const int nb = kb + 2;
        if (nb < KT) load_stage(nb, nb % GSTG);
        cp_commit();
        cp_wait<2>();
        __syncthreads();

        const __nv_bfloat16* base = sm + (kb % GSTG) * STAGE_ELEMS;
        const __nv_bfloat16* sAh = base;
        const __nv_bfloat16* sAl = base + SA_ELEMS;
        const __nv_bfloat16* sBh = base + 2 * SA_ELEMS;
        const __nv_bfloat16* sBl = base + 2 * SA_ELEMS + SB_ELEMS;

#pragma unroll
        for (int kc = 0; kc < 2; kc++) {
            const int col = kc * 16 + lcol8;
            uint32_t ah[4][4], al[4][4];
#pragma unroll
            for (int mt = 0; mt < 4; mt++) {
                const int row = wm * 64 + mt * 16 + lrow;
                ldm_x4(ah[mt][0], ah[mt][1], ah[mt][2], ah[mt][3],
                       smem_u32(sAh + row * GLD + col));
                ldm_x4(al[mt][0], al[mt][1], al[mt][2], al[mt][3],
                       smem_u32(sAl + row * GLD + col));
            }
#pragma unroll
            for (int nt2 = 0; nt2 < 4; nt2++) {
                const int row = wn * 64 + nt2 * 16 + lrow;
                uint32_t r0, r1, r2, r3, s0, s1, s2, s3;
                ldm_x4(r0, r1, r2, r3, smem_u32(sBh + row * GLD + col));
                ldm_x4(s0, s1, s2, s3, smem_u32(sBl + row * GLD + col));
                uint32_t bh0[2] = {r0, r2}, bh1[2] = {r1, r3};
                uint32_t bl0[2] = {s0, s2}, bl1[2] = {s1, s3};
#pragma unroll
                for (int mt = 0; mt < 4; mt++) {
                    mma_bf16(acc[mt][2*nt2], ah[mt], bh0);
                    mma_bf16(acc[mt][2*nt2], al[mt], bh0);
                    mma_bf16(acc[mt][2*nt2], ah[mt], bl0);
                    mma_bf16(acc[mt][2*nt2+1], ah[mt], bh1);
                    mma_bf16(acc[mt][2*nt2+1], al[mt], bh1);
                    mma_bf16(acc[mt][2*nt2+1], ah[mt], bl1);
                }
            }
        }
        __syncthreads();
    }

    // epilogue
#pragma unroll
    for (int mt = 0; mt < 4; mt++)
#pragma unroll
        for (int nt = 0; nt < 8; nt++) {
            const int row0 = m0 + wm * 64 + mt * 16 + g;
            const int col  = n0 + wn * 64 + nt * 8 + tq * 2;
            if (OUT == 0) {
                *(float2*)(C + (size_t)row0 * D_ + col) =
                    make_float2(acc[mt][nt][0], acc[mt][nt][1]);
                *(float2*)(C + (size_t)(row0 + 8) * D_ + col) =
                    make_float2(acc[mt][nt][2], acc[mt][nt][3]);
            } else if (OUT == 1) {
                uint32_t hi, lo;
                split_pack(acc[mt][nt][0], acc[mt][nt][1], hi, lo);
                *(uint32_t*)(Chg + (size_t)row0 * D_ + col) = hi;
                *(uint32_t*)(Clg + (size_t)row0 * D_ + col) = lo;
                split_pack(acc[mt][nt][2], acc[mt][nt][3], hi, lo);
                *(uint32_t*)(Chg + (size_t)(row0 + 8) * D_ + col) = hi;
                *(uint32_t*)(Clg + (size_t)(row0 + 8) * D_ + col) = lo;
            } else {
                // RoPE: col pair (even, odd) within head; i = (col%128)/2, s = token % S_
                const int i = (col & (HD_ - 1)) >> 1;
#pragma unroll
                for (int half = 0; half < 2; half++) {
                    const int row = row0 + half * 8;
                    const int s = row & (S_ - 1);
                    const float c = fc[s * (HD_/2) + i];
                    const float sn = fs[s * (HD_/2) + i];
                    const float x0 = acc[mt][nt][2*half], x1 = acc[mt][nt][2*half+1];
                    const float o0 = x0 * c - x1 * sn;
                    const float o1 = x0 * sn + x1 * c;
                    uint32_t hi, lo;
                    split_pack(o0, o1, hi, lo);
                    *(uint32_t*)(Chg + (size_t)row * D_ + col) = hi;
                    *(uint32_t*)(Clg + (size_t)row * D_ + col) = lo;
                }
            }
        }
}

// ---------------- flash attention (round-2, unchanged) ----------------
#define ALD 136
#define AQ_ELEMS (128 * ALD)
#define AKV_ELEMS (64 * ALD)

__global__ __launch_bounds__(256, 1)
void attn_kernel(const __nv_bfloat16* __restrict__ Qh, const __nv_bfloat16* __restrict__ Ql,
                 const __nv_bfloat16* __restrict__ Kh, const __nv_bfloat16* __restrict__ Kl,
                 const __nv_bfloat16* __restrict__ Vh, const __nv_bfloat16* __restrict__ Vl,
                 __nv_bfloat16* __restrict__ Oh, __nv_bfloat16* __restrict__ Ol) {
    extern __shared__ __align__(16) __nv_bfloat16 smn[];
    __nv_bfloat16* sQh = smn;
    __nv_bfloat16* sQl = sQh + AQ_ELEMS;
    __nv_bfloat16* sKV = sQl + AQ_ELEMS;

    const int tid = threadIdx.x;
    const int wid = tid >> 5, lane = tid & 31;
    const int g = lane >> 2, tq = lane & 3;
    const int qt = blockIdx.x, h = blockIdx.y, b = blockIdx.z;
    const int lrow = lane & 15, lcol8 = (lane >> 4) << 3;
    const float scale = 0.08838834764831845f;

    {
#pragma unroll
        for (int p = 0; p < 8; p++) {
            int c = tid + p * 256;
            int row = c >> 4;
            int col8 = (c & 15) << 3;
            size_t goff = ((size_t)(b * S_ + qt * 128 + row)) * D_ + h * HD_ + col8;
            cp16(sQh + row * ALD + col8, Qh + goff);
            cp16(sQl + row * ALD + col8, Ql + goff);
        }
    }

    auto load_kv = [&](int j, int buf) {
        __nv_bfloat16* base = sKV + buf * 4 * AKV_ELEMS;
#pragma unroll
        for (int p = 0; p < 4; p++) {
            int c = tid + p * 256;
            int row = c >> 4;
            int col8 = (c & 15) << 3;
            size_t goff = ((size_t)(b * S_ + j * 64 + row)) * D_ + h * HD_ + col8;
            cp16(base + 0 * AKV_ELEMS + row * ALD + col8, Kh + goff);
            cp16(base + 1 * AKV_ELEMS + row * ALD + col8, Kl + goff);
            cp16(base + 2 * AKV_ELEMS + row * ALD + col8, Vh + goff);
            cp16(base + 3 * AKV_ELEMS + row * ALD + col8, Vl + goff);
        }
    };

    const int jmax = 2 * qt + 1;
    load_kv(0, 0); cp_commit();

    float oacc[16][4];
#pragma unroll
    for (int i = 0; i < 16; i++)
#pragma unroll
        for (int e = 0; e < 4; e++) oacc[i][e] = 0.f;
    float sm2[2] = {-1e30f, -1e30f};
    float sl2[2] = {0.f, 0.f};

    for (int j = 0; j <= jmax; ++j) {
        if (j + 1 <= jmax) load_kv(j + 1, (j + 1) & 1);
        cp_commit();
        cp_wait<1>();
        __syncthreads();

        const __nv_bfloat16* base = sKV + (j & 1) * 4 * AKV_ELEMS;
        const __nv_bfloat16* sKh = base;
        const __nv_bfloat16* sKl = base + 1 * AKV_ELEMS;
        const __nv_bfloat16* sVh = base + 2 * AKV_ELEMS;
        const __nv_bfloat16* sVl = base + 3 * AKV_ELEMS;

        float sacc[8][4];
#pragma unroll
        for (int i = 0; i < 8; i++)
#pragma unroll
            for (int e = 0; e < 4; e++) sacc[i][e] = 0.f;

#pragma unroll
        for (int kc = 0; kc < 8; kc++) {
            uint32_t qh[4], ql[4];
            int qrow = wid * 16 + lrow;
            int col = kc * 16 + lcol8;
            ldm_x4(qh[0], qh[1], qh[2], qh[3], smem_u32(sQh + qrow * ALD + col));
            ldm_x4(ql[0], ql[1], ql[2], ql[3], smem_u32(sQl + qrow * ALD + col));
#pragma unroll
            for (int nt2 = 0; nt2 < 4; nt2++) {
                int krow = nt2 * 16 + lrow;
                uint32_t r0, r1, r2, r3, s0, s1, s2, s3;
                ldm_x4(r0, r1, r2, r3, smem_u32(sKh + krow * ALD + col));
                ldm_x4(s0, s1, s2, s3, smem_u32(sKl + krow * ALD + col));
                uint32_t bh0[2] = {r0, r2}, bh1[2] = {r1, r3};
                uint32_t bl0[2] = {s0, s2}, bl1[2] = {s1, s3};
                mma_bf16(sacc[2*nt2], qh, bh0);
                mma_bf16(sacc[2*nt2], ql, bh0);
                mma_bf16(sacc[2*nt2], qh, bl0);
                mma_bf16(sacc[2*nt2+1], qh, bh1);
                mma_bf16(sacc[2*nt2+1], ql, bh1);
                mma_bf16(sacc[2*nt2+1], qh, bl1);
            }
        }

        const int qg0 = qt * 128 + wid * 16 + g;
        const bool need_mask = (j >= 2 * qt);
        float mx0 = -1e30f, mx1 = -1e30f;
#pragma unroll
        for (int nt = 0; nt < 8; nt++) {
            int kg = j * 64 + nt * 8 + tq * 2;
#pragma unroll
            for (int e = 0; e < 4; e++) {
                float sv = sacc[nt][e] * scale;
                int row = (e < 2) ? qg0 : (qg0 + 8);
                int col = kg + (e & 1);
                if (need_mask && col > row) sv = -1e30f;
                sacc[nt][e] = sv;
                if (e < 2) mx0 = fmaxf(mx0, sv); else mx1 = fmaxf(mx1, sv);
            }
        }
        mx0 = fmaxf(mx0, __shfl_xor_sync(0xffffffffu, mx0, 1));
        mx0 = fmaxf(mx0, __shfl_xor_sync(0xffffffffu, mx0, 2));
        mx1 = fmaxf(mx1, __shfl_xor_sync(0xffffffffu, mx1, 1));
        mx1 = fmaxf(mx1, __shfl_xor_sync(0xffffffffu, mx1, 2));

        float mn0 = fmaxf(sm2[0], mx0), mn1 = fmaxf(sm2[1], mx1);
        float al0 = __expf(sm2[0] - mn0), al1 = __expf(sm2[1] - mn1);
        sm2[0] = mn0; sm2[1] = mn1;

        float rs0 = 0.f, rs1 = 0.f;
#pragma unroll
        for (int nt = 0; nt < 8; nt++)
#pragma unroll
            for (int e = 0; e < 4; e++) {
                float pv = __expf(sacc[nt][e] - ((e < 2) ? mn0 : mn1));
                sacc[nt][e] = pv;
                if (e < 2) rs0 += pv; else rs1 += pv;
            }
        rs0 += __shfl_xor_sync(0xffffffffu, rs0, 1);
        rs0 += __shfl_xor_sync(0xffffffffu, rs0, 2);
        rs1 += __shfl_xor_sync(0xffffffffu, rs1, 1);
        rs1 += __shfl_xor_sync(0xffffffffu, rs1, 2);
        sl2[0] = sl2[0] * al0 + rs0;
        sl2[1] = sl2[1] * al1 + rs1;

#pragma unroll
        for (int dt = 0; dt < 16; dt++) {
            oacc[dt][0] *= al0; oacc[dt][1] *= al0;
            oacc[dt][2] *= al1; oacc[dt][3] *= al1;
        }

#pragma unroll
        for (int kc = 0; kc < 4; kc++) {
            uint32_t ph[4], pl[4];
            split_pack(sacc[2*kc][0],   sacc[2*kc][1],   ph[0], pl[0]);
            split_pack(sacc[2*kc][2],   sacc[2*kc][3],   ph[1], pl[1]);
            split_pack(sacc[2*kc+1][0], sacc[2*kc+1][1], ph[2], pl[2]);
            split_pack(sacc[2*kc+1][2], sacc[2*kc+1][3], ph[3], pl[3]);
#pragma unroll
            for (int dt2 = 0; dt2 < 8; dt2++) {
                int vrow = kc * 16 + lrow;
                int col = dt2 * 16 + lcol8;
                uint32_t r0, r1, r2, r3, s0, s1, s2, s3;
                ldm_x4_t(r0, r1, r2, r3, smem_u32(sVh + vrow * ALD + col));
                ldm_x4_t(s0, s1, s2, s3, smem_u32(sVl + vrow * ALD + col));
                uint32_t vh0[2] = {r0, r1}, vh1[2] = {r2, r3};
                uint32_t vl0[2] = {s0, s1}, vl1[2] = {s2, s3};
                mma_bf16(oacc[2*dt2], ph, vh0);
                mma_bf16(oacc[2*dt2], pl, vh0);
                mma_bf16(oacc[2*dt2], ph, vl0);
                mma_bf16(oacc[2*dt2+1], ph, vh1);
                mma_bf16(oacc[2*dt2+1], pl, vh1);
                mma_bf16(oacc[2*dt2+1], ph, vl1);
            }
        }
        __syncthreads();
    }

    float inv0 = 1.f / sl2[0];
    float inv1 = 1.f / sl2[1];
    int s0r = qt * 128 + wid * 16 + g;
#pragma unroll
    for (int dt = 0; dt < 16; dt++) {
        int col = h * HD_ + dt * 8 + tq * 2;
        uint32_t hi, lo;
        split_pack(oacc[dt][0] * inv0, oacc[dt][1] * inv0, hi, lo);
        *(uint32_t*)(Oh + ((size_t)(b * S_ + s0r)) * D_ + col) = hi;
        *(uint32_t*)(Ol + ((size_t)(b * S_ + s0r)) * D_ + col) = lo;
        split_pack(oacc[dt][2] * inv1, oacc[dt][3] * inv1, hi, lo);
        *(uint32_t*)(Oh + ((size_t)(b * S_ + s0r + 8)) * D_ + col) = hi;
        *(uint32_t*)(Ol + ((size_t)(b * S_ + s0r + 8)) * D_ + col) = lo;
    }
}

// ---------------- launch ----------------
extern "C" void kernel_launch(void* const* d_in, const int* in_sizes, int n_in,
                              void* d_out, int out_size) {
    const float* x  = (const float*)d_in[0];
    const float* fc = (const float*)d_in[1];
    const float* fs = (const float*)d_in[2];
    const float* wq = (const float*)d_in[4];
    const float* wk = (const float*)d_in[5];
    const float* wv = (const float*)d_in[6];
    const float* wo = (const float*)d_in[7];
    float* out = (float*)d_out;

    __nv_bfloat16 *xh, *xl, *wqh, *wql, *wkh, *wkl, *wvh, *wvl, *woh, *wol;
    __nv_bfloat16 *qh, *ql, *kh, *kl, *vh, *vl, *ah, *al;
    cudaGetSymbolAddress((void**)&xh, g_xh);   cudaGetSymbolAddress((void**)&xl, g_xl);
    cudaGetSymbolAddress((void**)&wqh, g_wqh); cudaGetSymbolAddress((void**)&wql, g_wql);
    cudaGetSymbolAddress((void**)&wkh, g_wkh); cudaGetSymbolAddress((void**)&wkl, g_wkl);
    cudaGetSymbolAddress((void**)&wvh, g_wvh); cudaGetSymbolAddress((void**)&wvl, g_wvl);
    cudaGetSymbolAddress((void**)&woh, g_woh); cudaGetSymbolAddress((void**)&wol, g_wol);
    cudaGetSymbolAddress((void**)&qh, g_qh);   cudaGetSymbolAddress((void**)&ql, g_ql);
    cudaGetSymbolAddress((void**)&kh, g_kh);   cudaGetSymbolAddress((void**)&kl, g_kl);
    cudaGetSymbolAddress((void**)&vh, g_vh);   cudaGetSymbolAddress((void**)&vl, g_vl);
    cudaGetSymbolAddress((void**)&ah, g_ah);   cudaGetSymbolAddress((void**)&al, g_al);

    const int n4 = (int)(NELEM / 4);
    const int cvb = (n4 + 255) / 256;
    cvt_split<<<cvb, 256>>>((const float4*)x,  (uint2*)xh,  (uint2*)xl,  n4);
    cvt_split<<<cvb, 256>>>((const float4*)wq, (uint2*)wqh, (uint2*)wql, n4);
    cvt_split<<<cvb, 256>>>((const float4*)wk, (uint2*)wkh, (uint2*)wkl, n4);
    cvt_split<<<cvb, 256>>>((const float4*)wv, (uint2*)wvh, (uint2*)wvl, n4);
    cvt_split<<<cvb, 256>>>((const float4*)wo, (uint2*)woh, (uint2*)wol, n4);

    cudaFuncSetAttribute(gemm_nt<0>, cudaFuncAttributeMaxDynamicSharedMemorySize, GEMM_SMEM);
    cudaFuncSetAttribute(gemm_nt<1>, cudaFuncAttributeMaxDynamicSharedMemorySize, GEMM_SMEM);
    cudaFuncSetAttribute(gemm_nt<2>, cudaFuncAttributeMaxDynamicSharedMemorySize, GEMM_SMEM);

    dim3 gg(MTOK / GBM, D_ / GBN);   // (32, 16); x (M tiles) fastest -> B slab reuse in L2
    gemm_nt<2><<<gg, 256, GEMM_SMEM>>>(xh, xl, wqh, wql, nullptr, qh, ql, fc, fs);
    gemm_nt<2><<<gg, 256, GEMM_SMEM>>>(xh, xl, wkh, wkl, nullptr, kh, kl, fc, fs);
    gemm_nt<1><<<gg, 256, GEMM_SMEM>>>(xh, xl, wvh, wvl, nullptr, vh, vl, nullptr, nullptr);

    const int attn_smem = (2 * AQ_ELEMS + 2 * 4 * AKV_ELEMS) * (int)sizeof(__nv_bfloat16);
    cudaFuncSetAttribute(attn_kernel, cudaFuncAttributeMaxDynamicSharedMemorySize, attn_smem);
    attn_kernel<<<dim3(S_ / 128, H_, B_), 256, attn_smem>>>(qh, ql, kh, kl, vh, vl, ah, al);

    gemm_nt<0><<<gg, 256, GEMM_SMEM>>>(ah, al, woh, wol, out, nullptr, nullptr, nullptr, nullptr);
}

// round 5
// speedup vs baseline: 2.8626x; 2.8626x over previous
#include <cuda_runtime.h>
#include <cuda_fp16.h>
#include <cstdint>

#define B_  2
#define S_  2048
#define D_  4096
#define H_  32
#define HD_ 128
#define MTOK (B_*S_)
#define NELEM ((size_t)MTOK * D_)

// ---------------- scratch (allocation-free) ----------------
__device__ __half g_x[NELEM];
__device__ __half g_wq[NELEM], g_wk[NELEM], g_wv[NELEM], g_wo[NELEM];
__device__ __half g_q[NELEM], g_k[NELEM], g_v[NELEM], g_a[NELEM];

// ---------------- helpers ----------------
__device__ __forceinline__ uint32_t smem_u32(const void* p) {
    return (uint32_t)__cvta_generic_to_shared(p);
}
__device__ __forceinline__ void cp16(void* dst, const void* src) {
    asm volatile("cp.async.cg.shared.global [%0], [%1], 16;"
                 :: "r"(smem_u32(dst)), "l"(src) : "memory");
}
__device__ __forceinline__ void cp_commit() {
    asm volatile("cp.async.commit_group;" ::: "memory");
}
template<int N>
__device__ __forceinline__ void cp_wait() {
    asm volatile("cp.async.wait_group %0;" :: "n"(N) : "memory");
}
__device__ __forceinline__ void ldm_x4(uint32_t& r0, uint32_t& r1, uint32_t& r2, uint32_t& r3, uint32_t addr) {
    asm volatile("ldmatrix.sync.aligned.m8n8.x4.shared.b16 {%0,%1,%2,%3}, [%4];"
                 : "=r"(r0), "=r"(r1), "=r"(r2), "=r"(r3) : "r"(addr));
}
__device__ __forceinline__ void ldm_x4_t(uint32_t& r0, uint32_t& r1, uint32_t& r2, uint32_t& r3, uint32_t addr) {
    asm volatile("ldmatrix.sync.aligned.m8n8.x4.trans.shared.b16 {%0,%1,%2,%3}, [%4];"
                 : "=r"(r0), "=r"(r1), "=r"(r2), "=r"(r3) : "r"(addr));
}
__device__ __forceinline__ void mma_f16(float* c, const uint32_t* a, const uint32_t* b) {
    asm volatile(
        "mma.sync.aligned.m16n8k16.row.col.f32.f16.f16.f32 "
        "{%0,%1,%2,%3}, {%4,%5,%6,%7}, {%8,%9}, {%0,%1,%2,%3};"
        : "+f"(c[0]), "+f"(c[1]), "+f"(c[2]), "+f"(c[3])
        : "r"(a[0]), "r"(a[1]), "r"(a[2]), "r"(a[3]), "r"(b[0]), "r"(b[1]));
}
__device__ __forceinline__ uint32_t pack_h2(float a, float b) {
    __half2 h = __floats2half2_rn(a, b);
    return *(uint32_t*)&h;
}

// ---------------- convert: fp32 -> fp16 ----------------
__global__ void cvt_h(const float4* __restrict__ in, uint2* __restrict__ out, int n4) {
    int i = blockIdx.x * blockDim.x + threadIdx.x;
    if (i >= n4) return;
    float4 v = in[i];
    out[i] = make_uint2(pack_h2(v.x, v.y), pack_h2(v.z, v.w));
}

// ============ GEMM: C[M,N] = A[M,K]*B[N,K]^T, fp16, 128x128x32, 4-stage ============
#define GBM 128
#define GBN 128
#define GBK 32
#define GLD 40                        // padded smem row stride (halves)
#define GSTG 4
#define SA_ELEMS (GBM * GLD)          // 5120
#define STAGE_ELEMS (2 * SA_ELEMS)    // A + B = 10240 halves = 20KB
#define GEMM_SMEM (GSTG * STAGE_ELEMS * 2)   // 80KB

// OUT: 0 = fp32 C ; 1 = fp16 C ; 2 = RoPE + fp16 C
template<int OUT>
__global__ __launch_bounds__(256, 2)
void gemm_nt(const __half* __restrict__ Ag, const __half* __restrict__ Bg,
             float* __restrict__ C, __half* __restrict__ Ch,
             const float* __restrict__ fc, const float* __restrict__ fs) {
    extern __shared__ __align__(16) __half sm[];

    const int tid = threadIdx.x;
    const int wid = tid >> 5, lane = tid & 31;
    const int wm = wid >> 2, wn = wid & 3;        // 2 x 4 warp grid, warp tile 64x32
    const int m0 = blockIdx.x * GBM, n0 = blockIdx.y * GBN;
    const int lrow = lane & 15, lcol8 = (lane >> 4) << 3;
    const int g = lane >> 2, tq = lane & 3;
    const int K = D_;

    float acc[4][4][4];
#pragma unroll
    for (int i = 0; i < 4; i++)
#pragma unroll
        for (int j = 0; j < 4; j++)
#pragma unroll
            for (int e = 0; e < 4; e++) acc[i][j][e] = 0.f;

    auto load_stage = [&](int kb, int buf) {
        __half* base = sm + buf * STAGE_ELEMS;
        const int k0 = kb * GBK;
#pragma unroll
        for (int p = 0; p < 4; p++) {
            const int t = tid + p * 256;          // 0..1023
            const int arr = t >> 9;               // 0=A, 1=B
            const int i = t & 511;
            const int row = i >> 2, col8 = (i & 3) << 3;
            const __half* gsrc = (arr ? Bg : Ag) + (size_t)((arr ? n0 : m0) + row) * K + k0 + col8;
            cp16(base + arr * SA_ELEMS + row * GLD + col8, gsrc);
        }
    };

    const int KT = K / GBK;            // 128
    load_stage(0, 0); cp_commit();
    load_stage(1, 1); cp_commit();
    load_stage(2, 2); cp_commit();

    for (int kb = 0; kb < KT; kb++) {
        const int nb = kb + 3;
        if (nb < KT) load_stage(nb, nb & 3);
        cp_commit();
        cp_wait<3>();
        __syncthreads();

        const __half* sA = sm + (kb & 3) * STAGE_ELEMS;
        const __half* sB = sA + SA_ELEMS;

#pragma unroll
        for (int kc = 0; kc < 2; kc++) {
            const int col = kc * 16 + lcol8;
            uint32_t a[4][4];
#pragma unroll
            for (int mt = 0; mt < 4; mt++) {
                const int row = wm * 64 + mt * 16 + lrow;
                ldm_x4(a[mt][0], a[mt][1], a[mt][2], a[mt][3],
                       smem_u32(sA + row * GLD + col));
            }
            uint32_t b[4][2];
#pragma unroll
            for (int nt2 = 0; nt2 < 2; nt2++) {
                const int row = wn * 32 + nt2 * 16 + lrow;
                uint32_t r0, r1, r2, r3;
                ldm_x4(r0, r1, r2, r3, smem_u32(sB + row * GLD + col));
                b[2*nt2][0] = r0; b[2*nt2][1] = r2;
                b[2*nt2+1][0] = r1; b[2*nt2+1][1] = r3;
            }
#pragma unroll
            for (int mt = 0; mt < 4; mt++)
#pragma unroll
                for (int nt = 0; nt < 4; nt++)
                    mma_f16(acc[mt][nt], a[mt], b[nt]);
        }
        __syncthreads();
    }

    // epilogue
#pragma unroll
    for (int mt = 0; mt < 4; mt++)
#pragma unroll
        for (int nt = 0; nt < 4; nt++) {
            const int row0 = m0 + wm * 64 + mt * 16 + g;
            const int col  = n0 + wn * 32 + nt * 8 + tq * 2;
            if (OUT == 0) {
                *(float2*)(C + (size_t)row0 * D_ + col) =
                    make_float2(acc[mt][nt][0], acc[mt][nt][1]);
                *(float2*)(C + (size_t)(row0 + 8) * D_ + col) =
                    make_float2(acc[mt][nt][2], acc[mt][nt][3]);
            } else if (OUT == 1) {
                *(uint32_t*)(Ch + (size_t)row0 * D_ + col) =
                    pack_h2(acc[mt][nt][0], acc[mt][nt][1]);
                *(uint32_t*)(Ch + (size_t)(row0 + 8) * D_ + col) =
                    pack_h2(acc[mt][nt][2], acc[mt][nt][3]);
            } else {
                const int i = (col & (HD_ - 1)) >> 1;
#pragma unroll
                for (int half = 0; half < 2; half++) {
                    const int row = row0 + half * 8;
                    const int s = row & (S_ - 1);
                    const float c = fc[s * (HD_/2) + i];
                    const float sn = fs[s * (HD_/2) + i];
                    const float x0 = acc[mt][nt][2*half], x1 = acc[mt][nt][2*half+1];
                    *(uint32_t*)(Ch + (size_t)row * D_ + col) =
                        pack_h2(x0 * c - x1 * sn, x0 * sn + x1 * c);
                }
            }
        }
}

// ---------------- flash attention (fp16, cp.async, KV double-buffer) ----------------
#define ALD 136
#define AQ_ELEMS (128 * ALD)
#define AKV_ELEMS (64 * ALD)
#define ATTN_SMEM ((AQ_ELEMS + 2 * 2 * AKV_ELEMS) * 2)   // 104448 B

__global__ __launch_bounds__(256, 1)
void attn_kernel(const __half* __restrict__ Q, const __half* __restrict__ Kg,
                 const __half* __restrict__ Vg, __half* __restrict__ O) {
    extern __shared__ __align__(16) __half smn[];
    __half* sQ = smn;
    __half* sKV = sQ + AQ_ELEMS;   // [2 stages][K,V][64*ALD]

    const int tid = threadIdx.x;
    const int wid = tid >> 5, lane = tid & 31;
    const int g = lane >> 2, tq = lane & 3;
    const int qt = blockIdx.x, h = blockIdx.y, b = blockIdx.z;
    const int lrow = lane & 15, lcol8 = (lane >> 4) << 3;
    const float scale = 0.08838834764831845f;

    // Q tile: 128 rows x 128 cols = 2048 16B-chunks
    {
#pragma unroll
        for (int p = 0; p < 8; p++) {
            int c = tid + p * 256;
            int row = c >> 4;
            int col8 = (c & 15) << 3;
            size_t goff = ((size_t)(b * S_ + qt * 128 + row)) * D_ + h * HD_ + col8;
            cp16(sQ + row * ALD + col8, Q + goff);
        }
    }

    auto load_kv = [&](int j, int buf) {
        __half* base = sKV + buf * 2 * AKV_ELEMS;
#pragma unroll
        for (int p = 0; p < 8; p++) {
            int c = tid + p * 256;          // 0..2047
            int arr = c >> 10;              // 0=K, 1=V
            int idx = c & 1023;
            int row = idx >> 4;
            int col8 = (idx & 15) << 3;
            size_t goff = ((size_t)(b * S_ + j * 64 + row)) * D_ + h * HD_ + col8;
            cp16(base + arr * AKV_ELEMS + row * ALD + col8, (arr ? Vg : Kg) + goff);
        }
    };

    const int jmax = 2 * qt + 1;
    load_kv(0, 0); cp_commit();

    float oacc[16][4];
#pragma unroll
    for (int i = 0; i < 16; i++)
#pragma unroll
        for (int e = 0; e < 4; e++) oacc[i][e] = 0.f;
    float sm2[2] = {-1e30f, -1e30f};
    float sl2[2] = {0.f, 0.f};

    for (int j = 0; j <= jmax; ++j) {
        if (j + 1 <= jmax) load_kv(j + 1, (j + 1) & 1);
        cp_commit();
        cp_wait<1>();
        __syncthreads();

        const __half* sK = sKV + (j & 1) * 2 * AKV_ELEMS;
        const __half* sV = sK + AKV_ELEMS;

        // S = Q K^T
        float sacc[8][4];
#pragma unroll
        for (int i = 0; i < 8; i++)
#pragma unroll
            for (int e = 0; e < 4; e++) sacc[i][e] = 0.f;

#pragma unroll
        for (int kc = 0; kc < 8; kc++) {
            uint32_t qf[4];
            int qrow = wid * 16 + lrow;
            int col = kc * 16 + lcol8;
            ldm_x4(qf[0], qf[1], qf[2], qf[3], smem_u32(sQ + qrow * ALD + col));
#pragma unroll
            for (int nt2 = 0; nt2 < 4; nt2++) {
                int krow = nt2 * 16 + lrow;
                uint32_t r0, r1, r2, r3;
                ldm_x4(r0, r1, r2, r3, smem_u32(sK + krow * ALD + col));
                uint32_t b0[2] = {r0, r2}, b1[2] = {r1, r3};
                mma_f16(sacc[2*nt2], qf, b0);
                mma_f16(sacc[2*nt2+1], qf, b1);
            }
        }

        // scale + causal mask + online softmax
        const int qg0 = qt * 128 + wid * 16 + g;
        const bool need_mask = (j >= 2 * qt);
        float mx0 = -1e30f, mx1 = -1e30f;
#pragma unroll
        for (int nt = 0; nt < 8; nt++) {
            int kg = j * 64 + nt * 8 + tq * 2;
#pragma unroll
            for (int e = 0; e < 4; e++) {
                float sv = sacc[nt][e] * scale;
                int row = (e < 2) ? qg0 : (qg0 + 8);
                int col = kg + (e & 1);
                if (need_mask && col > row) sv = -1e30f;
                sacc[nt][e] = sv;
                if (e < 2) mx0 = fmaxf(mx0, sv); else mx1 = fmaxf(mx1, sv);
            }
        }
        mx0 = fmaxf(mx0, __shfl_xor_sync(0xffffffffu, mx0, 1));
        mx0 = fmaxf(mx0, __shfl_xor_sync(0xffffffffu, mx0, 2));
        mx1 = fmaxf(mx1, __shfl_xor_sync(0xffffffffu, mx1, 1));
        mx1 = fmaxf(mx1, __shfl_xor_sync(0xffffffffu, mx1, 2));

        float mn0 = fmaxf(sm2[0], mx0), mn1 = fmaxf(sm2[1], mx1);
        float al0 = __expf(sm2[0] - mn0), al1 = __expf(sm2[1] - mn1);
        sm2[0] = mn0; sm2[1] = mn1;

        float rs0 = 0.f, rs1 = 0.f;
#pragma unroll
        for (int nt = 0; nt < 8; nt++)
#pragma unroll
            for (int e = 0; e < 4; e++) {
                float pv = __expf(sacc[nt][e] - ((e < 2) ? mn0 : mn1));
                sacc[nt][e] = pv;
                if (e < 2) rs0 += pv; else rs1 += pv;
            }
        rs0 += __shfl_xor_sync(0xffffffffu, rs0, 1);
        rs0 += __shfl_xor_sync(0xffffffffu, rs0, 2);
        rs1 += __shfl_xor_sync(0xffffffffu, rs1, 1);
        rs1 += __shfl_xor_sync(0xffffffffu, rs1, 2);
        sl2[0] = sl2[0] * al0 + rs0;
        sl2[1] = sl2[1] * al1 + rs1;

#pragma unroll
        for (int dt = 0; dt < 16; dt++) {
            oacc[dt][0] *= al0; oacc[dt][1] *= al0;
            oacc[dt][2] *= al1; oacc[dt][3] *= al1;
        }

        // O += P V
#pragma unroll
        for (int kc = 0; kc < 4; kc++) {
            uint32_t pf[4];
            pf[0] = pack_h2(sacc[2*kc][0],   sacc[2*kc][1]);
            pf[1] = pack_h2(sacc[2*kc][2],   sacc[2*kc][3]);
            pf[2] = pack_h2(sacc[2*kc+1][0], sacc[2*kc+1][1]);
            pf[3] = pack_h2(sacc[2*kc+1][2], sacc[2*kc+1][3]);
#pragma unroll
            for (int dt2 = 0; dt2 < 8; dt2++) {
                int vrow = kc * 16 + lrow;
                int col = dt2 * 16 + lcol8;
                uint32_t r0, r1, r2, r3;
                ldm_x4_t(r0, r1, r2, r3, smem_u32(sV + vrow * ALD + col));
                uint32_t v0[2] = {r0, r1}, v1[2] = {r2, r3};
                mma_f16(oacc[2*dt2], pf, v0);
                mma_f16(oacc[2*dt2+1], pf, v1);
            }
        }
        __syncthreads();
    }

    // epilogue: normalize + write fp16
    float inv0 = 1.f / sl2[0];
    float inv1 = 1.f / sl2[1];
    int s0r = qt * 128 + wid * 16 + g;
#pragma unroll
    for (int dt = 0; dt < 16; dt++) {
        int col = h * HD_ + dt * 8 + tq * 2;
        *(uint32_t*)(O + ((size_t)(b * S_ + s0r)) * D_ + col) =
            pack_h2(oacc[dt][0] * inv0, oacc[dt][1] * inv0);
        *(uint32_t*)(O + ((size_t)(b * S_ + s0r + 8)) * D_ + col) =
            pack_h2(oacc[dt][2] * inv1, oacc[dt][3] * inv1);
    }
}

// ---------------- launch ----------------
extern "C" void kernel_launch(void* const* d_in, const int* in_sizes, int n_in,
                              void* d_out, int out_size) {
    const float* x  = (const float*)d_in[0];
    const float* fc = (const float*)d_in[1];
    const float* fs = (const float*)d_in[2];
    const float* wq = (const float*)d_in[4];
    const float* wk = (const float*)d_in[5];
    const float* wv = (const float*)d_in[6];
    const float* wo = (const float*)d_in[7];
    float* out = (float*)d_out;

    __half *xh, *wqh, *wkh, *wvh, *woh, *qh, *kh, *vh, *ah;
    cudaGetSymbolAddress((void**)&xh, g_x);
    cudaGetSymbolAddress((void**)&wqh, g_wq);
    cudaGetSymbolAddress((void**)&wkh, g_wk);
    cudaGetSymbolAddress((void**)&wvh, g_wv);
    cudaGetSymbolAddress((void**)&woh, g_wo);
    cudaGetSymbolAddress((void**)&qh, g_q);
    cudaGetSymbolAddress((void**)&kh, g_k);
    cudaGetSymbolAddress((void**)&vh, g_v);
    cudaGetSymbolAddress((void**)&ah, g_a);

    const int n4 = (int)(NELEM / 4);
    const int cvb = (n4 + 255) / 256;
    cvt_h<<<cvb, 256>>>((const float4*)x,  (uint2*)xh,  n4);
    cvt_h<<<cvb, 256>>>((const float4*)wq, (uint2*)wqh, n4);
    cvt_h<<<cvb, 256>>>((const float4*)wk, (uint2*)wkh, n4);
    cvt_h<<<cvb, 256>>>((const float4*)wv, (uint2*)wvh, n4);
    cvt_h<<<cvb, 256>>>((const float4*)wo, (uint2*)woh, n4);

    cudaFuncSetAttribute(gemm_nt<0>, cudaFuncAttributeMaxDynamicSharedMemorySize, GEMM_SMEM);
    cudaFuncSetAttribute(gemm_nt<1>, cudaFuncAttributeMaxDynamicSharedMemorySize, GEMM_SMEM);
    cudaFuncSetAttribute(gemm_nt<2>, cudaFuncAttributeMaxDynamicSharedMemorySize, GEMM_SMEM);

    dim3 gg(MTOK / GBM, D_ / GBN);   // (32, 32); x (M tiles) fastest -> B slab reuse in L2
    gemm_nt<2><<<gg, 256, GEMM_SMEM>>>(xh, wqh, nullptr, qh, fc, fs);
    gemm_nt<2><<<gg, 256, GEMM_SMEM>>>(xh, wkh, nullptr, kh, fc, fs);
    gemm_nt<1><<<gg, 256, GEMM_SMEM>>>(xh, wvh, nullptr, vh, nullptr, nullptr);

    cudaFuncSetAttribute(attn_kernel, cudaFuncAttributeMaxDynamicSharedMemorySize, ATTN_SMEM);
    attn_kernel<<<dim3(S_ / 128, H_, B_), 256, ATTN_SMEM>>>(qh, kh, vh, ah);

    gemm_nt<0><<<gg, 256, GEMM_SMEM>>>(ah, woh, out, nullptr, nullptr, nullptr);
}

// round 6
// speedup vs baseline: 3.0558x; 1.0675x over previous
#include <cuda_runtime.h>
#include <cuda_fp16.h>
#include <cstdint>

#define B_  2
#define S_  2048
#define D_  4096
#define H_  32
#define HD_ 128
#define MTOK (B_*S_)
#define NELEM ((size_t)MTOK * D_)

// ---------------- scratch (allocation-free) ----------------
__device__ __half g_x[NELEM];
__device__ __half g_wq[NELEM], g_wk[NELEM], g_wv[NELEM], g_wo[NELEM];
__device__ __half g_q[NELEM], g_k[NELEM], g_v[NELEM], g_a[NELEM];

// ---------------- helpers ----------------
__device__ __forceinline__ uint32_t smem_u32(const void* p) {
    return (uint32_t)__cvta_generic_to_shared(p);
}
__device__ __forceinline__ void cp16(void* dst, const void* src) {
    asm volatile("cp.async.cg.shared.global [%0], [%1], 16;"
                 :: "r"(smem_u32(dst)), "l"(src) : "memory");
}
__device__ __forceinline__ void cp_commit() {
    asm volatile("cp.async.commit_group;" ::: "memory");
}
template<int N>
__device__ __forceinline__ void cp_wait() {
    asm volatile("cp.async.wait_group %0;" :: "n"(N) : "memory");
}
__device__ __forceinline__ void ldm_x4(uint32_t& r0, uint32_t& r1, uint32_t& r2, uint32_t& r3, uint32_t addr) {
    asm volatile("ldmatrix.sync.aligned.m8n8.x4.shared.b16 {%0,%1,%2,%3}, [%4];"
                 : "=r"(r0), "=r"(r1), "=r"(r2), "=r"(r3) : "r"(addr));
}
__device__ __forceinline__ void ldm_x4_t(uint32_t& r0, uint32_t& r1, uint32_t& r2, uint32_t& r3, uint32_t addr) {
    asm volatile("ldmatrix.sync.aligned.m8n8.x4.trans.shared.b16 {%0,%1,%2,%3}, [%4];"
                 : "=r"(r0), "=r"(r1), "=r"(r2), "=r"(r3) : "r"(addr));
}
__device__ __forceinline__ void mma_f16(float* c, const uint32_t* a, const uint32_t* b) {
    asm volatile(
        "mma.sync.aligned.m16n8k16.row.col.f32.f16.f16.f32 "
        "{%0,%1,%2,%3}, {%4,%5,%6,%7}, {%8,%9}, {%0,%1,%2,%3};"
        : "+f"(c[0]), "+f"(c[1]), "+f"(c[2]), "+f"(c[3])
        : "r"(a[0]), "r"(a[1]), "r"(a[2]), "r"(a[3]), "r"(b[0]), "r"(b[1]));
}
__device__ __forceinline__ uint32_t pack_h2(float a, float b) {
    __half2 h = __floats2half2_rn(a, b);
    return *(uint32_t*)&h;
}

// ---------------- convert: fp32 -> fp16, 5 tensors in one launch ----------------
__global__ void cvt_h5(const float4* __restrict__ s0, const float4* __restrict__ s1,
                       const float4* __restrict__ s2, const float4* __restrict__ s3,
                       const float4* __restrict__ s4,
                       uint2* __restrict__ d0, uint2* __restrict__ d1,
                       uint2* __restrict__ d2, uint2* __restrict__ d3,
                       uint2* __restrict__ d4, int n4) {
    int i = blockIdx.x * blockDim.x + threadIdx.x;
    if (i >= n4) return;
    const int z = blockIdx.y;
    const float4* s = (z == 0) ? s0 : (z == 1) ? s1 : (z == 2) ? s2 : (z == 3) ? s3 : s4;
    uint2* d = (z == 0) ? d0 : (z == 1) ? d1 : (z == 2) ? d2 : (z == 3) ? d3 : d4;
    float4 v = s[i];
    d[i] = make_uint2(pack_h2(v.x, v.y), pack_h2(v.z, v.w));
}

// ============ GEMM mainloop: acc = A[M,K]*B[N,K]^T tile, fp16, 128x128x32, 4-stage ============
#define GBM 128
#define GBN 128
#define GBK 32
#define GLD 40
#define SA_ELEMS (GBM * GLD)          // 5120 halves
#define STAGE_ELEMS (2 * SA_ELEMS)    // 20KB
#define GEMM_SMEM (4 * STAGE_ELEMS * 2)   // 80KB

__device__ __forceinline__ void gemm_main(
    float acc[4][4][4], const __half* __restrict__ Ag, const __half* __restrict__ Bg,
    int m0, int n0, __half* sm, int tid, int wm, int wn, int lrow, int lcol8) {

    auto load_stage = [&](int kb, int buf) {
        __half* base = sm + buf * STAGE_ELEMS;
        const int k0 = kb * GBK;
#pragma unroll
        for (int p = 0; p < 4; p++) {
            const int t = tid + p * 256;          // 0..1023
            const int arr = t >> 9;               // 0=A, 1=B
            const int i = t & 511;
            const int row = i >> 2, col8 = (i & 3) << 3;
            const __half* gsrc = (arr ? Bg : Ag) + (size_t)((arr ? n0 : m0) + row) * D_ + k0 + col8;
            cp16(base + arr * SA_ELEMS + row * GLD + col8, gsrc);
        }
    };

    const int KT = D_ / GBK;           // 128
    load_stage(0, 0); cp_commit();
    load_stage(1, 1); cp_commit();
    load_stage(2, 2); cp_commit();

    for (int kb = 0; kb < KT; kb++) {
        cp_wait<2>();                  // stage kb's own copies landed
        __syncthreads();               // everyone's copies landed + everyone left iter kb-1
        if (kb + 3 < KT) load_stage(kb + 3, (kb + 3) & 3);   // overwrites buf (kb-1)&3: safe now
        cp_commit();                   // unconditional: keeps group-count invariant in tail

        const __half* sA = sm + (kb & 3) * STAGE_ELEMS;
        const __half* sB = sA + SA_ELEMS;

#pragma unroll
        for (int kc = 0; kc < 2; kc++) {
            const int col = kc * 16 + lcol8;
            uint32_t a[4][4];
#pragma unroll
            for (int mt = 0; mt < 4; mt++) {
                const int row = wm * 64 + mt * 16 + lrow;
                ldm_x4(a[mt][0], a[mt][1], a[mt][2], a[mt][3],
                       smem_u32(sA + row * GLD + col));
            }
            uint32_t b[4][2];
#pragma unroll
            for (int nt2 = 0; nt2 < 2; nt2++) {
                const int row = wn * 32 + nt2 * 16 + lrow;
                uint32_t r0, r1, r2, r3;
                ldm_x4(r0, r1, r2, r3, smem_u32(sB + row * GLD + col));
                b[2*nt2][0] = r0; b[2*nt2][1] = r2;
                b[2*nt2+1][0] = r1; b[2*nt2+1][1] = r3;
            }
#pragma unroll
            for (int mt = 0; mt < 4; mt++)
#pragma unroll
                for (int nt = 0; nt < 4; nt++)
                    mma_f16(acc[mt][nt], a[mt], b[nt]);
        }
    }
}

// ---- fused QKV GEMM: z=0 -> q (rope), z=1 -> k (rope), z=2 -> v (plain fp16) ----
__global__ __launch_bounds__(256, 2)
void qkv_gemm(const __half* __restrict__ Ag,
              const __half* __restrict__ W0, const __half* __restrict__ W1,
              const __half* __restrict__ W2,
              __half* __restrict__ C0, __half* __restrict__ C1, __half* __restrict__ C2,
              const float* __restrict__ fc, const float* __restrict__ fs) {
    extern __shared__ __align__(16) __half sm[];
    const int tid = threadIdx.x;
    const int wid = tid >> 5, lane = tid & 31;
    const int wm = wid >> 2, wn = wid & 3;
    const int m0 = blockIdx.x * GBM, n0 = blockIdx.y * GBN;
    const int lrow = lane & 15, lcol8 = (lane >> 4) << 3;
    const int g = lane >> 2, tq = lane & 3;
    const int z = blockIdx.z;
    const __half* Bg = (z == 0) ? W0 : (z == 1) ? W1 : W2;
    __half* Ch = (z == 0) ? C0 : (z == 1) ? C1 : C2;
    const bool dorope = (z < 2);

    float acc[4][4][4];
#pragma unroll
    for (int i = 0; i < 4; i++)
#pragma unroll
        for (int j = 0; j < 4; j++)
#pragma unroll
            for (int e = 0; e < 4; e++) acc[i][j][e] = 0.f;

    gemm_main(acc, Ag, Bg, m0, n0, sm, tid, wm, wn, lrow, lcol8);

#pragma unroll
    for (int mt = 0; mt < 4; mt++)
#pragma unroll
        for (int nt = 0; nt < 4; nt++) {
            const int row0 = m0 + wm * 64 + mt * 16 + g;
            const int col  = n0 + wn * 32 + nt * 8 + tq * 2;
            if (dorope) {
                const int i = (col & (HD_ - 1)) >> 1;
#pragma unroll
                for (int half = 0; half < 2; half++) {
                    const int row = row0 + half * 8;
                    const int s = row & (S_ - 1);
                    const float c = fc[s * (HD_/2) + i];
                    const float sn = fs[s * (HD_/2) + i];
                    const float x0 = acc[mt][nt][2*half], x1 = acc[mt][nt][2*half+1];
                    *(uint32_t*)(Ch + (size_t)row * D_ + col) =
                        pack_h2(x0 * c - x1 * sn, x0 * sn + x1 * c);
                }
            } else {
                *(uint32_t*)(Ch + (size_t)row0 * D_ + col) =
                    pack_h2(acc[mt][nt][0], acc[mt][nt][1]);
                *(uint32_t*)(Ch + (size_t)(row0 + 8) * D_ + col) =
                    pack_h2(acc[mt][nt][2], acc[mt][nt][3]);
            }
        }
}

// ---- output-projection GEMM: fp32 C ----
__global__ __launch_bounds__(256, 2)
void gemm_out(const __half* __restrict__ Ag, const __half* __restrict__ Bg,
              float* __restrict__ C) {
    extern __shared__ __align__(16) __half sm[];
    const int tid = threadIdx.x;
    const int wid = tid >> 5, lane = tid & 31;
    const int wm = wid >> 2, wn = wid & 3;
    const int m0 = blockIdx.x * GBM, n0 = blockIdx.y * GBN;
    const int lrow = lane & 15, lcol8 = (lane >> 4) << 3;
    const int g = lane >> 2, tq = lane & 3;

    float acc[4][4][4];
#pragma unroll
    for (int i = 0; i < 4; i++)
#pragma unroll
        for (int j = 0; j < 4; j++)
#pragma unroll
            for (int e = 0; e < 4; e++) acc[i][j][e] = 0.f;

    gemm_main(acc, Ag, Bg, m0, n0, sm, tid, wm, wn, lrow, lcol8);

#pragma unroll
    for (int mt = 0; mt < 4; mt++)
#pragma unroll
        for (int nt = 0; nt < 4; nt++) {
            const int row0 = m0 + wm * 64 + mt * 16 + g;
            const int col  = n0 + wn * 32 + nt * 8 + tq * 2;
            *(float2*)(C + (size_t)row0 * D_ + col) =
                make_float2(acc[mt][nt][0], acc[mt][nt][1]);
            *(float2*)(C + (size_t)(row0 + 8) * D_ + col) =
                make_float2(acc[mt][nt][2], acc[mt][nt][3]);
        }
}

// ---------------- flash attention (fp16, single-sync pipeline, reversed qt) ----------------
#define ALD 136
#define AQ_ELEMS (128 * ALD)
#define AKV_ELEMS (64 * ALD)
#define ATTN_SMEM ((AQ_ELEMS + 2 * 2 * AKV_ELEMS) * 2)   // 104448 B

__global__ __launch_bounds__(256, 1)
void attn_kernel(const __half* __restrict__ Q, const __half* __restrict__ Kg,
                 const __half* __restrict__ Vg, __half* __restrict__ O) {
    extern __shared__ __align__(16) __half smn[];
    __half* sQ = smn;
    __half* sKV = sQ + AQ_ELEMS;

    const int tid = threadIdx.x;
    const int wid = tid >> 5, lane = tid & 31;
    const int g = lane >> 2, tq = lane & 3;
    const int qt = (int)gridDim.x - 1 - (int)blockIdx.x;   // heavy CTAs first
    const int h = blockIdx.y, b = blockIdx.z;
    const int lrow = lane & 15, lcol8 = (lane >> 4) << 3;
    const float scale = 0.08838834764831845f;

    auto load_kv = [&](int j, int buf) {
        __half* base = sKV + buf * 2 * AKV_ELEMS;
#pragma unroll
        for (int p = 0; p < 8; p++) {
            int c = tid + p * 256;
            int arr = c >> 10;
            int idx = c & 1023;
            int row = idx >> 4;
            int col8 = (idx & 15) << 3;
            size_t goff = ((size_t)(b * S_ + j * 64 + row)) * D_ + h * HD_ + col8;
            cp16(base + arr * AKV_ELEMS + row * ALD + col8, (arr ? Vg : Kg) + goff);
        }
    };

    // prologue: Q + KV(0) in group 0
    {
#pragma unroll
        for (int p = 0; p < 8; p++) {
            int c = tid + p * 256;
            int row = c >> 4;
            int col8 = (c & 15) << 3;
            size_t goff = ((size_t)(b * S_ + qt * 128 + row)) * D_ + h * HD_ + col8;
            cp16(sQ + row * ALD + col8, Q + goff);
        }
    }
    load_kv(0, 0);
    cp_commit();

    float oacc[16][4];
#pragma unroll
    for (int i = 0; i < 16; i++)
#pragma unroll
        for (int e = 0; e < 4; e++) oacc[i][e] = 0.f;
    float sm2[2] = {-1e30f, -1e30f};
    float sl2[2] = {0.f, 0.f};

    const int jmax = 2 * qt + 1;
    for (int j = 0; j <= jmax; ++j) {
        cp_wait<0>();                  // KV(j) (+Q on j=0) landed for this thread
        __syncthreads();               // landed for all threads + all left iter j-1
        if (j + 1 <= jmax) load_kv(j + 1, (j + 1) & 1);   // overwrites buf (j-1)&1: safe
        cp_commit();

        const __half* sK = sKV + (j & 1) * 2 * AKV_ELEMS;
        const __half* sV = sK + AKV_ELEMS;

        // S = Q K^T
        float sacc[8][4];
#pragma unroll
        for (int i = 0; i < 8; i++)
#pragma unroll
            for (int e = 0; e < 4; e++) sacc[i][e] = 0.f;

#pragma unroll
        for (int kc = 0; kc < 8; kc++) {
            uint32_t qf[4];
            int qrow = wid * 16 + lrow;
            int col = kc * 16 + lcol8;
            ldm_x4(qf[0], qf[1], qf[2], qf[3], smem_u32(sQ + qrow * ALD + col));
#pragma unroll
            for (int nt2 = 0; nt2 < 4; nt2++) {
                int krow = nt2 * 16 + lrow;
                uint32_t r0, r1, r2, r3;
                ldm_x4(r0, r1, r2, r3, smem_u32(sK + krow * ALD + col));
                uint32_t b0[2] = {r0, r2}, b1[2] = {r1, r3};
                mma_f16(sacc[2*nt2], qf, b0);
                mma_f16(sacc[2*nt2+1], qf, b1);
            }
        }

        // scale + causal mask + online softmax
        const int qg0 = qt * 128 + wid * 16 + g;
        const bool need_mask = (j >= 2 * qt);
        float mx0 = -1e30f, mx1 = -1e30f;
#pragma unroll
        for (int nt = 0; nt < 8; nt++) {
            int kg = j * 64 + nt * 8 + tq * 2;
#pragma unroll
            for (int e = 0; e < 4; e++) {
                float sv = sacc[nt][e] * scale;
                int row = (e < 2) ? qg0 : (qg0 + 8);
                int col = kg + (e & 1);
                if (need_mask && col > row) sv = -1e30f;
                sacc[nt][e] = sv;
                if (e < 2) mx0 = fmaxf(mx0, sv); else mx1 = fmaxf(mx1, sv);
            }
        }
        mx0 = fmaxf(mx0, __shfl_xor_sync(0xffffffffu, mx0, 1));
        mx0 = fmaxf(mx0, __shfl_xor_sync(0xffffffffu, mx0, 2));
        mx1 = fmaxf(mx1, __shfl_xor_sync(0xffffffffu, mx1, 1));
        mx1 = fmaxf(mx1, __shfl_xor_sync(0xffffffffu, mx1, 2));

        float mn0 = fmaxf(sm2[0], mx0), mn1 = fmaxf(sm2[1], mx1);
        float al0 = __expf(sm2[0] - mn0), al1 = __expf(sm2[1] - mn1);
        sm2[0] = mn0; sm2[1] = mn1;

        float rs0 = 0.f, rs1 = 0.f;
#pragma unroll
        for (int nt = 0; nt < 8; nt++)
#pragma unroll
            for (int e = 0; e < 4; e++) {
                float pv = __expf(sacc[nt][e] - ((e < 2) ? mn0 : mn1));
                sacc[nt][e] = pv;
                if (e < 2) rs0 += pv; else rs1 += pv;
            }
        rs0 += __shfl_xor_sync(0xffffffffu, rs0, 1);
        rs0 += __shfl_xor_sync(0xffffffffu, rs0, 2);
        rs1 += __shfl_xor_sync(0xffffffffu, rs1, 1);
        rs1 += __shfl_xor_sync(0xffffffffu, rs1, 2);
        sl2[0] = sl2[0] * al0 + rs0;
        sl2[1] = sl2[1] * al1 + rs1;

#pragma unroll
        for (int dt = 0; dt < 16; dt++) {
            oacc[dt][0] *= al0; oacc[dt][1] *= al0;
            oacc[dt][2] *= al1; oacc[dt][3] *= al1;
        }

        // O += P V
#pragma unroll
        for (int kc = 0; kc < 4; kc++) {
            uint32_t pf[4];
            pf[0] = pack_h2(sacc[2*kc][0],   sacc[2*kc][1]);
            pf[1] = pack_h2(sacc[2*kc][2],   sacc[2*kc][3]);
            pf[2] = pack_h2(sacc[2*kc+1][0], sacc[2*kc+1][1]);
            pf[3] = pack_h2(sacc[2*kc+1][2], sacc[2*kc+1][3]);
#pragma unroll
            for (int dt2 = 0; dt2 < 8; dt2++) {
                int vrow = kc * 16 + lrow;
                int col = dt2 * 16 + lcol8;
                uint32_t r0, r1, r2, r3;
                ldm_x4_t(r0, r1, r2, r3, smem_u32(sV + vrow * ALD + col));
                uint32_t v0[2] = {r0, r1}, v1[2] = {r2, r3};
                mma_f16(oacc[2*dt2], pf, v0);
                mma_f16(oacc[2*dt2+1], pf, v1);
            }
        }
    }

    // epilogue: normalize + write fp16
    float inv0 = 1.f / sl2[0];
    float inv1 = 1.f / sl2[1];
    int s0r = qt * 128 + wid * 16 + g;
#pragma unroll
    for (int dt = 0; dt < 16; dt++) {
        int col = h * HD_ + dt * 8 + tq * 2;
        *(uint32_t*)(O + ((size_t)(b * S_ + s0r)) * D_ + col) =
            pack_h2(oacc[dt][0] * inv0, oacc[dt][1] * inv0);
        *(uint32_t*)(O + ((size_t)(b * S_ + s0r + 8)) * D_ + col) =
            pack_h2(oacc[dt][2] * inv1, oacc[dt][3] * inv1);
    }
}

// ---------------- launch ----------------
extern "C" void kernel_launch(void* const* d_in, const int* in_sizes, int n_in,
                              void* d_out, int out_size) {
    const float* x  = (const float*)d_in[0];
    const float* fc = (const float*)d_in[1];
    const float* fs = (const float*)d_in[2];
    const float* wq = (const float*)d_in[4];
    const float* wk = (const float*)d_in[5];
    const float* wv = (const float*)d_in[6];
    const float* wo = (const float*)d_in[7];
    float* out = (float*)d_out;

    __half *xh, *wqh, *wkh, *wvh, *woh, *qh, *kh, *vh, *ah;
    cudaGetSymbolAddress((void**)&xh, g_x);
    cudaGetSymbolAddress((void**)&wqh, g_wq);
    cudaGetSymbolAddress((void**)&wkh, g_wk);
    cudaGetSymbolAddress((void**)&wvh, g_wv);
    cudaGetSymbolAddress((void**)&woh, g_wo);
    cudaGetSymbolAddress((void**)&qh, g_q);
    cudaGetSymbolAddress((void**)&kh, g_k);
    cudaGetSymbolAddress((void**)&vh, g_v);
    cudaGetSymbolAddress((void**)&ah, g_a);

    const int n4 = (int)(NELEM / 4);
    cvt_h5<<<dim3((n4 + 255) / 256, 5), 256>>>(
        (const float4*)x, (const float4*)wq, (const float4*)wk,
        (const float4*)wv, (const float4*)wo,
        (uint2*)xh, (uint2*)wqh, (uint2*)wkh, (uint2*)wvh, (uint2*)woh, n4);

    cudaFuncSetAttribute(qkv_gemm, cudaFuncAttributeMaxDynamicSharedMemorySize, GEMM_SMEM);
    cudaFuncSetAttribute(gemm_out, cudaFuncAttributeMaxDynamicSharedMemorySize, GEMM_SMEM);

    dim3 gq(MTOK / GBM, D_ / GBN, 3);
    qkv_gemm<<<gq, 256, GEMM_SMEM>>>(xh, wqh, wkh, wvh, qh, kh, vh, fc, fs);

    cudaFuncSetAttribute(attn_kernel, cudaFuncAttributeMaxDynamicSharedMemorySize, ATTN_SMEM);
    attn_kernel<<<dim3(S_ / 128, H_, B_), 256, ATTN_SMEM>>>(qh, kh, vh, ah);

    dim3 gg(MTOK / GBM, D_ / GBN);
    gemm_out<<<gg, 256, GEMM_SMEM>>>(ah, woh, out);
}